// round 1
// baseline (speedup 1.0000x reference)
#include <cuda_runtime.h>
#include <math.h>

// Problem constants
#define B_ 4
#define S_ 2048
#define E_ 1024
#define MQ (B_*S_)          // 8192 rows for QKV projection

// GEMM tiling
#define BM 128
#define BN 128
#define BK 16
#define TM 8
#define TN 8
#define NTHREADS 256        // (BM/TM)*(BN/TN)

// Scratch (static device globals; allocation-free per harness rules)
__device__ float g_Q[(size_t)B_*S_*E_];
__device__ float g_K[(size_t)B_*S_*E_];
__device__ float g_V[(size_t)B_*S_*E_];
__device__ float g_P[(size_t)B_*S_*S_];

// ---------------------------------------------------------------------------
// C[m,n] = alpha * sum_k A[m,k]*B[n,k] (+ bias[n])      (both K-major, "NT")
// batched via blockIdx.z with element strides sA/sB/sC.
// All dims assumed multiples of tile sizes (true for this problem).
// ---------------------------------------------------------------------------
__global__ __launch_bounds__(NTHREADS)
void gemm_nt(const float* __restrict__ A, const float* __restrict__ Bm,
             const float* __restrict__ bias, float* __restrict__ C,
             int M, int N, int K, float alpha,
             long sA, long sB, long sC)
{
    A  += (long)blockIdx.z * sA;
    Bm += (long)blockIdx.z * sB;
    C  += (long)blockIdx.z * sC;

    __shared__ float As[BK][BM + 4];
    __shared__ float Bs[BK][BN + 4];

    const int tid = threadIdx.x;
    const int tx = tid & 15;          // 0..15
    const int ty = tid >> 4;          // 0..15
    const int m0 = blockIdx.y * BM;
    const int n0 = blockIdx.x * BN;

    const int lrow = tid >> 2;        // 0..63
    const int lcol = (tid & 3) * 4;   // 0,4,8,12

    float acc[TM][TN];
    #pragma unroll
    for (int i = 0; i < TM; i++)
        #pragma unroll
        for (int j = 0; j < TN; j++)
            acc[i][j] = 0.f;

    for (int k0 = 0; k0 < K; k0 += BK) {
        #pragma unroll
        for (int i = 0; i < 2; i++) {
            int r = lrow + i * 64;
            float4 v = *reinterpret_cast<const float4*>(&A[(long)(m0 + r) * K + k0 + lcol]);
            As[lcol + 0][r] = v.x; As[lcol + 1][r] = v.y;
            As[lcol + 2][r] = v.z; As[lcol + 3][r] = v.w;
        }
        #pragma unroll
        for (int i = 0; i < 2; i++) {
            int r = lrow + i * 64;
            float4 v = *reinterpret_cast<const float4*>(&Bm[(long)(n0 + r) * K + k0 + lcol]);
            Bs[lcol + 0][r] = v.x; Bs[lcol + 1][r] = v.y;
            Bs[lcol + 2][r] = v.z; Bs[lcol + 3][r] = v.w;
        }
        __syncthreads();

        #pragma unroll
        for (int k = 0; k < BK; k++) {
            float ra[TM], rb[TN];
            #pragma unroll
            for (int i = 0; i < TM; i++) ra[i] = As[k][ty * TM + i];
            #pragma unroll
            for (int j = 0; j < TN; j++) rb[j] = Bs[k][tx * TN + j];
            #pragma unroll
            for (int i = 0; i < TM; i++)
                #pragma unroll
                for (int j = 0; j < TN; j++)
                    acc[i][j] += ra[i] * rb[j];
        }
        __syncthreads();
    }

    #pragma unroll
    for (int i = 0; i < TM; i++) {
        long m = m0 + ty * TM + i;
        #pragma unroll
        for (int j = 0; j < TN; j += 4) {
            int n = n0 + tx * TN + j;
            float4 o;
            o.x = acc[i][j + 0] * alpha;
            o.y = acc[i][j + 1] * alpha;
            o.z = acc[i][j + 2] * alpha;
            o.w = acc[i][j + 3] * alpha;
            if (bias) {
                float4 bv = *reinterpret_cast<const float4*>(&bias[n]);
                o.x += bv.x; o.y += bv.y; o.z += bv.z; o.w += bv.w;
            }
            *reinterpret_cast<float4*>(&C[m * N + n]) = o;
        }
    }
}

// ---------------------------------------------------------------------------
// C[m,n] = alpha * sum_k A[m,k]*B[k,n]                  ("NN")
// ---------------------------------------------------------------------------
__global__ __launch_bounds__(NTHREADS)
void gemm_nn(const float* __restrict__ A, const float* __restrict__ Bm,
             float* __restrict__ C,
             int M, int N, int K, float alpha,
             long sA, long sB, long sC)
{
    A  += (long)blockIdx.z * sA;
    Bm += (long)blockIdx.z * sB;
    C  += (long)blockIdx.z * sC;

    __shared__ float As[BK][BM + 4];
    __shared__ float Bs[BK][BN + 4];

    const int tid = threadIdx.x;
    const int tx = tid & 15;
    const int ty = tid >> 4;
    const int m0 = blockIdx.y * BM;
    const int n0 = blockIdx.x * BN;

    const int lrow = tid >> 2;        // 0..63  (A tile)
    const int lcol = (tid & 3) * 4;   // 0,4,8,12
    const int krow = tid >> 5;        // 0..7   (B tile)
    const int ncol = (tid & 31) * 4;  // 0..124

    float acc[TM][TN];
    #pragma unroll
    for (int i = 0; i < TM; i++)
        #pragma unroll
        for (int j = 0; j < TN; j++)
            acc[i][j] = 0.f;

    for (int k0 = 0; k0 < K; k0 += BK) {
        #pragma unroll
        for (int i = 0; i < 2; i++) {
            int r = lrow + i * 64;
            float4 v = *reinterpret_cast<const float4*>(&A[(long)(m0 + r) * K + k0 + lcol]);
            As[lcol + 0][r] = v.x; As[lcol + 1][r] = v.y;
            As[lcol + 2][r] = v.z; As[lcol + 3][r] = v.w;
        }
        #pragma unroll
        for (int i = 0; i < 2; i++) {
            int kr = krow + i * 8;
            float4 v = *reinterpret_cast<const float4*>(&Bm[(long)(k0 + kr) * N + n0 + ncol]);
            *reinterpret_cast<float4*>(&Bs[kr][ncol]) = v;
        }
        __syncthreads();

        #pragma unroll
        for (int k = 0; k < BK; k++) {
            float ra[TM], rb[TN];
            #pragma unroll
            for (int i = 0; i < TM; i++) ra[i] = As[k][ty * TM + i];
            #pragma unroll
            for (int j = 0; j < TN; j++) rb[j] = Bs[k][tx * TN + j];
            #pragma unroll
            for (int i = 0; i < TM; i++)
                #pragma unroll
                for (int j = 0; j < TN; j++)
                    acc[i][j] += ra[i] * rb[j];
        }
        __syncthreads();
    }

    #pragma unroll
    for (int i = 0; i < TM; i++) {
        long m = m0 + ty * TM + i;
        #pragma unroll
        for (int j = 0; j < TN; j += 4) {
            int n = n0 + tx * TN + j;
            float4 o;
            o.x = acc[i][j + 0] * alpha;
            o.y = acc[i][j + 1] * alpha;
            o.z = acc[i][j + 2] * alpha;
            o.w = acc[i][j + 3] * alpha;
            *reinterpret_cast<float4*>(&C[m * N + n]) = o;
        }
    }
}

// ---------------------------------------------------------------------------
// Row softmax: one block (256 threads) per row of length S_=2048.
// ---------------------------------------------------------------------------
__global__ __launch_bounds__(256)
void softmax_rows(float* __restrict__ P)
{
    const long row = blockIdx.x;
    float* p = P + row * (long)S_;
    const int tid = threadIdx.x;

    float v[8];
    float mx = -INFINITY;
    #pragma unroll
    for (int i = 0; i < 8; i++) {
        v[i] = p[tid + i * 256];
        mx = fmaxf(mx, v[i]);
    }

    __shared__ float red[8];
    #pragma unroll
    for (int o = 16; o > 0; o >>= 1)
        mx = fmaxf(mx, __shfl_xor_sync(0xffffffffu, mx, o));
    if ((tid & 31) == 0) red[tid >> 5] = mx;
    __syncthreads();
    float m = red[0];
    #pragma unroll
    for (int i = 1; i < 8; i++) m = fmaxf(m, red[i]);
    __syncthreads();

    float s = 0.f;
    #pragma unroll
    for (int i = 0; i < 8; i++) {
        v[i] = __expf(v[i] - m);
        s += v[i];
    }
    #pragma unroll
    for (int o = 16; o > 0; o >>= 1)
        s += __shfl_xor_sync(0xffffffffu, s, o);
    if ((tid & 31) == 0) red[tid >> 5] = s;
    __syncthreads();
    float tot = 0.f;
    #pragma unroll
    for (int i = 0; i < 8; i++) tot += red[i];
    const float inv = 1.f / tot;

    #pragma unroll
    for (int i = 0; i < 8; i++)
        p[tid + i * 256] = v[i] * inv;
}

// ---------------------------------------------------------------------------
extern "C" void kernel_launch(void* const* d_in, const int* in_sizes, int n_in,
                              void* d_out, int out_size)
{
    const float* x  = (const float*)d_in[0];
    const float* wq = (const float*)d_in[1];
    const float* bq = (const float*)d_in[2];
    const float* wk = (const float*)d_in[3];
    const float* bk = (const float*)d_in[4];
    const float* wv = (const float*)d_in[5];
    const float* bv = (const float*)d_in[6];
    float* out = (float*)d_out;

    float *Q, *K, *V, *P;
    cudaGetSymbolAddress((void**)&Q, g_Q);
    cudaGetSymbolAddress((void**)&K, g_K);
    cudaGetSymbolAddress((void**)&V, g_V);
    cudaGetSymbolAddress((void**)&P, g_P);

    dim3 th(NTHREADS);

    // QKV projections: [8192,1024] = x[8192,1024] @ W^T[1024,1024] + b
    dim3 g1(E_ / BN, MQ / BM, 1);
    gemm_nt<<<g1, th>>>(x, wq, bq, Q, MQ, E_, E_, 1.f, 0, 0, 0);
    gemm_nt<<<g1, th>>>(x, wk, bk, K, MQ, E_, E_, 1.f, 0, 0, 0);
    gemm_nt<<<g1, th>>>(x, wv, bv, V, MQ, E_, E_, 1.f, 0, 0, 0);

    // scores = Q @ K^T / sqrt(E), per batch
    dim3 g2(S_ / BN, S_ / BM, B_);
    gemm_nt<<<g2, th>>>(Q, K, nullptr, P, S_, S_, E_, 0.03125f,
                        (long)S_ * E_, (long)S_ * E_, (long)S_ * S_);

    // row softmax over scores
    softmax_rows<<<B_ * S_, 256>>>(P);

    // out = P @ V, per batch
    dim3 g3(E_ / BN, S_ / BM, B_);
    gemm_nn<<<g3, th>>>(P, V, out, S_, E_, S_, 1.f,
                        (long)S_ * S_, (long)S_ * E_, (long)S_ * E_);
}

// round 3
// speedup vs baseline: 2.1758x; 2.1758x over previous
#include <cuda_runtime.h>
#include <cuda_bf16.h>
#include <math.h>
#include <stdint.h>

#define B_ 4
#define S_ 2048
#define E_ 1024
#define MQ (B_*S_)

// ---------------- device scratch (allocation-free) ----------------
__device__ __nv_bfloat16 g_xh[(size_t)MQ*E_], g_xl[(size_t)MQ*E_];
__device__ __nv_bfloat16 g_wh[3][(size_t)E_*E_], g_wl[3][(size_t)E_*E_];
__device__ __nv_bfloat16 g_Qh[(size_t)MQ*E_], g_Ql[(size_t)MQ*E_];
__device__ __nv_bfloat16 g_Kh[(size_t)MQ*E_], g_Kl[(size_t)MQ*E_];
__device__ __nv_bfloat16 g_Vh[(size_t)MQ*E_], g_Vl[(size_t)MQ*E_];     // V^T: [B][E][S]
__device__ float         g_P [(size_t)B_*S_*S_];
__device__ __nv_bfloat16 g_Ph[(size_t)B_*S_*S_], g_Pl[(size_t)B_*S_*S_];

// ---------------- helpers ----------------
__device__ __forceinline__ uint32_t smem_u32(const void* p) {
    uint32_t a;
    asm("{ .reg .u64 t; cvta.to.shared.u64 t, %1; cvt.u32.u64 %0, t; }" : "=r"(a) : "l"(p));
    return a;
}
__device__ __forceinline__ void cp16(uint32_t s, const void* g) {
    asm volatile("cp.async.cg.shared.global [%0], [%1], 16;" :: "r"(s), "l"(g) : "memory");
}
#define CP_COMMIT() asm volatile("cp.async.commit_group;" ::: "memory")
#define CP_WAIT1()  asm volatile("cp.async.wait_group 1;" ::: "memory")

__device__ __forceinline__ void ldsm4(uint32_t& r0, uint32_t& r1, uint32_t& r2, uint32_t& r3, uint32_t a) {
    asm volatile("ldmatrix.sync.aligned.m8n8.x4.shared.b16 {%0,%1,%2,%3}, [%4];"
                 : "=r"(r0), "=r"(r1), "=r"(r2), "=r"(r3) : "r"(a));
}
__device__ __forceinline__ void mma16816(float* c, const uint32_t* a, const uint32_t* b) {
    asm volatile("mma.sync.aligned.m16n8k16.row.col.f32.bf16.bf16.f32 "
                 "{%0,%1,%2,%3}, {%4,%5,%6,%7}, {%8,%9}, {%0,%1,%2,%3};"
                 : "+f"(c[0]), "+f"(c[1]), "+f"(c[2]), "+f"(c[3])
                 : "r"(a[0]), "r"(a[1]), "r"(a[2]), "r"(a[3]), "r"(b[0]), "r"(b[1]));
}

// ---------------- warp-MMA split-bf16 GEMM ----------------
// D[M,N] = alpha * (A @ B^T) (+ bias[n]); A,B as (hi,lo) bf16 pairs.
// modes: 0 = bf16 split row-major (Oh,Ol); 1 = bf16 split transposed [b][n][s] (V);
//        2/3 = fp32 Cf.
#define MT 128
#define NT 128
#define KT 32
#define NTH 256
#define NSTG 3
#define ASTR 40                       // bf16 elems/row (32 + 8 pad) -> 80 B
#define ARR_B (128*ASTR*2)            // 10240 B per tile array
#define STG_B (4*ARR_B)               // Ah, Al, Bh, Bl
#define SMEM_SZ (NSTG*STG_B)          // 122880 B

__global__ __launch_bounds__(NTH, 1)
void gemm_split(const __nv_bfloat16* __restrict__ Ah, const __nv_bfloat16* __restrict__ Al,
                const __nv_bfloat16* __restrict__ Bh, const __nv_bfloat16* __restrict__ Bl,
                const float* __restrict__ bias,
                float* __restrict__ Cf, __nv_bfloat16* __restrict__ Oh, __nv_bfloat16* __restrict__ Ol,
                int Ndim, int Kdim, float alpha,
                long sA, long sB, long sC, int mode)
{
    extern __shared__ char smem[];
    const uint32_t sb = smem_u32(smem);
    const int tid = threadIdx.x, lane = tid & 31, wid = tid >> 5;
    const int wm = (wid >> 2) * 64;          // warp M offset (0,64)
    const int wn = (wid & 3) * 32;           // warp N offset (0,32,64,96)
    const long z = blockIdx.z;
    Ah += z * sA; Al += z * sA; Bh += z * sB; Bl += z * sB;
    const int m0 = blockIdx.y * MT, n0 = blockIdx.x * NT;
    const int kt = Kdim / KT;

    // per-tile loader: 4 arrays x 512 16B-chunks; 8 chunks/thread
    auto load_tile = [&](int it, int stage) {
        const uint32_t st = sb + stage * STG_B;
        const long k0 = (long)it * KT;
        #pragma unroll
        for (int arr = 0; arr < 4; arr++) {
            const __nv_bfloat16* src = (arr == 0) ? Ah : (arr == 1) ? Al : (arr == 2) ? Bh : Bl;
            const int rbase = (arr < 2) ? m0 : n0;
            const uint32_t ab = st + arr * ARR_B;
            #pragma unroll
            for (int i = 0; i < 2; i++) {
                int c = tid + i * NTH;
                int row = c >> 2, kc = c & 3;
                cp16(ab + row * 80 + kc * 16,
                     src + (long)(rbase + row) * Kdim + k0 + kc * 8);
            }
        }
    };

    float acc[4][4][4];
    #pragma unroll
    for (int i = 0; i < 4; i++)
        #pragma unroll
        for (int j = 0; j < 4; j++)
            #pragma unroll
            for (int q = 0; q < 4; q++) acc[i][j][q] = 0.f;

    // ldmatrix per-thread offsets
    const uint32_t a_row = (lane & 15), a_k = (lane >> 4) * 8;
    const uint32_t b_n = ((lane >> 4) & 1) * 8 + (lane & 7), b_k = ((lane >> 3) & 1) * 8;

    load_tile(0, 0); CP_COMMIT();
    load_tile(1, 1); CP_COMMIT();

    for (int it = 0; it < kt; it++) {
        CP_WAIT1();                     // tile it complete (tile it+1 may pend)
        __syncthreads();                // visibility + all warps done with stage (it-1)%3
        if (it + 2 < kt) load_tile(it + 2, (it + 2) % NSTG);
        CP_COMMIT();

        const uint32_t st = sb + (it % NSTG) * STG_B;
        #pragma unroll
        for (int ks = 0; ks < 2; ks++) {
            uint32_t ah[4][4], al[4][4], bh[4][2], bl[4][2];
            #pragma unroll
            for (int i = 0; i < 4; i++) {
                uint32_t off = (wm + i * 16 + a_row) * 80 + (ks * 16 + a_k) * 2;
                ldsm4(ah[i][0], ah[i][1], ah[i][2], ah[i][3], st + off);
                ldsm4(al[i][0], al[i][1], al[i][2], al[i][3], st + ARR_B + off);
            }
            #pragma unroll
            for (int jj = 0; jj < 2; jj++) {
                uint32_t off = (wn + jj * 16 + b_n) * 80 + (ks * 16 + b_k) * 2;
                uint32_t r0, r1, r2, r3;
                ldsm4(r0, r1, r2, r3, st + 2 * ARR_B + off);
                bh[2 * jj][0] = r0; bh[2 * jj][1] = r1; bh[2 * jj + 1][0] = r2; bh[2 * jj + 1][1] = r3;
                ldsm4(r0, r1, r2, r3, st + 3 * ARR_B + off);
                bl[2 * jj][0] = r0; bl[2 * jj][1] = r1; bl[2 * jj + 1][0] = r2; bl[2 * jj + 1][1] = r3;
            }
            #pragma unroll
            for (int i = 0; i < 4; i++)
                #pragma unroll
                for (int j = 0; j < 4; j++) mma16816(acc[i][j], ah[i], bh[j]);
            #pragma unroll
            for (int i = 0; i < 4; i++)
                #pragma unroll
                for (int j = 0; j < 4; j++) mma16816(acc[i][j], ah[i], bl[j]);
            #pragma unroll
            for (int i = 0; i < 4; i++)
                #pragma unroll
                for (int j = 0; j < 4; j++) mma16816(acc[i][j], al[i], bh[j]);
        }
    }

    // ---------------- epilogue ----------------
    const int r = lane >> 2, cq = (lane & 3) * 2;

    if (mode == 1) {
        // stage hi/lo tiles in smem, then coalesced transposed store [b][n][s]
        __syncthreads();
        __nv_bfloat16* sh = reinterpret_cast<__nv_bfloat16*>(smem);
        __nv_bfloat16* sl = sh + 128 * 136;
        #pragma unroll
        for (int i = 0; i < 4; i++)
            #pragma unroll
            for (int j = 0; j < 4; j++) {
                const int cl = wn + j * 8 + cq;
                #pragma unroll
                for (int h = 0; h < 2; h++) {
                    const int row = wm + i * 16 + r + h * 8;
                    float v0 = acc[i][j][2 * h + 0] * alpha;
                    float v1 = acc[i][j][2 * h + 1] * alpha;
                    if (bias) { v0 += __ldg(bias + n0 + cl); v1 += __ldg(bias + n0 + cl + 1); }
                    __nv_bfloat16 h0 = __float2bfloat16(v0), h1 = __float2bfloat16(v1);
                    sh[row * 136 + cl]     = h0;
                    sh[row * 136 + cl + 1] = h1;
                    sl[row * 136 + cl]     = __float2bfloat16(v0 - __bfloat162float(h0));
                    sl[row * 136 + cl + 1] = __float2bfloat16(v1 - __bfloat162float(h1));
                }
            }
        __syncthreads();
        const int c = tid >> 1, half = tid & 1;
        const long bidx = (long)(m0 >> 11);
        const int sbase = (m0 & 2047) + half * 64;
        const long obase = bidx * E_ * S_ + (long)(n0 + c) * S_ + sbase;
        #pragma unroll
        for (int mm = 0; mm < 64; mm += 8) {
            const int m = half * 64 + mm;
            unsigned short uh[8], ul[8];
            #pragma unroll
            for (int t = 0; t < 8; t++) {
                uh[t] = __bfloat16_as_ushort(sh[(m + t) * 136 + c]);
                ul[t] = __bfloat16_as_ushort(sl[(m + t) * 136 + c]);
            }
            *reinterpret_cast<ushort4*>(Oh + obase + mm)     = make_ushort4(uh[0], uh[1], uh[2], uh[3]);
            *reinterpret_cast<ushort4*>(Oh + obase + mm + 4) = make_ushort4(uh[4], uh[5], uh[6], uh[7]);
            *reinterpret_cast<ushort4*>(Ol + obase + mm)     = make_ushort4(ul[0], ul[1], ul[2], ul[3]);
            *reinterpret_cast<ushort4*>(Ol + obase + mm + 4) = make_ushort4(ul[4], ul[5], ul[6], ul[7]);
        }
        return;
    }

    #pragma unroll
    for (int i = 0; i < 4; i++)
        #pragma unroll
        for (int j = 0; j < 4; j++) {
            const int gn = n0 + wn + j * 8 + cq;
            float bv0 = 0.f, bv1 = 0.f;
            if (bias) { bv0 = __ldg(bias + gn); bv1 = __ldg(bias + gn + 1); }
            #pragma unroll
            for (int h = 0; h < 2; h++) {
                const long gm = m0 + wm + i * 16 + r + h * 8;
                float v0 = acc[i][j][2 * h + 0] * alpha + bv0;
                float v1 = acc[i][j][2 * h + 1] * alpha + bv1;
                if (mode >= 2) {
                    *reinterpret_cast<float2*>(Cf + z * sC + gm * Ndim + gn) = make_float2(v0, v1);
                } else {
                    __nv_bfloat16 h0 = __float2bfloat16(v0), h1 = __float2bfloat16(v1);
                    __nv_bfloat16 l0 = __float2bfloat16(v0 - __bfloat162float(h0));
                    __nv_bfloat16 l1 = __float2bfloat16(v1 - __bfloat162float(h1));
                    *reinterpret_cast<ushort2*>(Oh + gm * Ndim + gn) =
                        make_ushort2(__bfloat16_as_ushort(h0), __bfloat16_as_ushort(h1));
                    *reinterpret_cast<ushort2*>(Ol + gm * Ndim + gn) =
                        make_ushort2(__bfloat16_as_ushort(l0), __bfloat16_as_ushort(l1));
                }
            }
        }
}

// ---------------- fp32 -> bf16 hi/lo split ----------------
__global__ __launch_bounds__(256)
void split_f32(const float* __restrict__ s, __nv_bfloat16* __restrict__ h,
               __nv_bfloat16* __restrict__ l, long n)
{
    long i = ((long)blockIdx.x * blockDim.x + threadIdx.x) * 4;
    if (i >= n) return;
    float4 v = *reinterpret_cast<const float4*>(s + i);
    float a[4] = {v.x, v.y, v.z, v.w};
    unsigned short hh[4], ll[4];
    #pragma unroll
    for (int k = 0; k < 4; k++) {
        __nv_bfloat16 hb = __float2bfloat16(a[k]);
        __nv_bfloat16 lb = __float2bfloat16(a[k] - __bfloat162float(hb));
        hh[k] = __bfloat16_as_ushort(hb); ll[k] = __bfloat16_as_ushort(lb);
    }
    *reinterpret_cast<ushort4*>(h + i) = make_ushort4(hh[0], hh[1], hh[2], hh[3]);
    *reinterpret_cast<ushort4*>(l + i) = make_ushort4(ll[0], ll[1], ll[2], ll[3]);
}

// ---------------- softmax -> bf16 split ----------------
__global__ __launch_bounds__(256)
void softmax_split(const float* __restrict__ P, __nv_bfloat16* __restrict__ Ph,
                   __nv_bfloat16* __restrict__ Pl)
{
    const long row = blockIdx.x;
    const float* p = P + row * (long)S_;
    const int tid = threadIdx.x;

    float v[8];
    float mx = -INFINITY;
    #pragma unroll
    for (int i = 0; i < 8; i++) { v[i] = p[tid + i * 256]; mx = fmaxf(mx, v[i]); }

    __shared__ float red[8];
    #pragma unroll
    for (int o = 16; o > 0; o >>= 1) mx = fmaxf(mx, __shfl_xor_sync(0xffffffffu, mx, o));
    if ((tid & 31) == 0) red[tid >> 5] = mx;
    __syncthreads();
    float m = red[0];
    #pragma unroll
    for (int i = 1; i < 8; i++) m = fmaxf(m, red[i]);
    __syncthreads();

    float sm = 0.f;
    #pragma unroll
    for (int i = 0; i < 8; i++) { v[i] = __expf(v[i] - m); sm += v[i]; }
    #pragma unroll
    for (int o = 16; o > 0; o >>= 1) sm += __shfl_xor_sync(0xffffffffu, sm, o);
    if ((tid & 31) == 0) red[tid >> 5] = sm;
    __syncthreads();
    float tot = 0.f;
    #pragma unroll
    for (int i = 0; i < 8; i++) tot += red[i];
    const float inv = 1.f / tot;

    #pragma unroll
    for (int i = 0; i < 8; i++) {
        float w = v[i] * inv;
        __nv_bfloat16 hb = __float2bfloat16(w);
        __nv_bfloat16 lb = __float2bfloat16(w - __bfloat162float(hb));
        Ph[row * (long)S_ + tid + i * 256] = hb;
        Pl[row * (long)S_ + tid + i * 256] = lb;
    }
}

// ---------------- launch ----------------
extern "C" void kernel_launch(void* const* d_in, const int* in_sizes, int n_in,
                              void* d_out, int out_size)
{
    const float* x  = (const float*)d_in[0];
    const float* wq = (const float*)d_in[1];
    const float* bq = (const float*)d_in[2];
    const float* wk = (const float*)d_in[3];
    const float* bk = (const float*)d_in[4];
    const float* wv = (const float*)d_in[5];
    const float* bv = (const float*)d_in[6];
    float* out = (float*)d_out;

    __nv_bfloat16 *xh, *xl, *wh, *wl, *Qh, *Ql, *Kh, *Kl, *Vh, *Vl, *Ph, *Pl;
    float* P;
    cudaGetSymbolAddress((void**)&xh, g_xh); cudaGetSymbolAddress((void**)&xl, g_xl);
    cudaGetSymbolAddress((void**)&wh, g_wh); cudaGetSymbolAddress((void**)&wl, g_wl);
    cudaGetSymbolAddress((void**)&Qh, g_Qh); cudaGetSymbolAddress((void**)&Ql, g_Ql);
    cudaGetSymbolAddress((void**)&Kh, g_Kh); cudaGetSymbolAddress((void**)&Kl, g_Kl);
    cudaGetSymbolAddress((void**)&Vh, g_Vh); cudaGetSymbolAddress((void**)&Vl, g_Vl);
    cudaGetSymbolAddress((void**)&P,  g_P);
    cudaGetSymbolAddress((void**)&Ph, g_Ph); cudaGetSymbolAddress((void**)&Pl, g_Pl);

    cudaFuncSetAttribute(gemm_split, cudaFuncAttributeMaxDynamicSharedMemorySize, SMEM_SZ);

    const long nx = (long)MQ * E_;
    const long nw = (long)E_ * E_;
    split_f32<<<(unsigned)((nx / 4 + 255) / 256), 256>>>(x,  xh, xl, nx);
    split_f32<<<(unsigned)((nw / 4 + 255) / 256), 256>>>(wq, wh + 0 * nw, wl + 0 * nw, nw);
    split_f32<<<(unsigned)((nw / 4 + 255) / 256), 256>>>(wk, wh + 1 * nw, wl + 1 * nw, nw);
    split_f32<<<(unsigned)((nw / 4 + 255) / 256), 256>>>(wv, wh + 2 * nw, wl + 2 * nw, nw);

    // QKV projections: M=8192, N=1024, K=1024
    dim3 g1(E_ / NT, MQ / MT, 1);
    gemm_split<<<g1, NTH, SMEM_SZ>>>(xh, xl, wh + 0 * nw, wl + 0 * nw, bq,
                                     nullptr, Qh, Ql, E_, E_, 1.f, 0, 0, 0, 0);
    gemm_split<<<g1, NTH, SMEM_SZ>>>(xh, xl, wh + 1 * nw, wl + 1 * nw, bk,
                                     nullptr, Kh, Kl, E_, E_, 1.f, 0, 0, 0, 0);
    gemm_split<<<g1, NTH, SMEM_SZ>>>(xh, xl, wh + 2 * nw, wl + 2 * nw, bv,
                                     nullptr, Vh, Vl, E_, E_, 1.f, 0, 0, 0, 1);

    // scores = Q @ K^T / 32 : per-batch M=N=2048, K=1024
    dim3 g2(S_ / NT, S_ / MT, B_);
    gemm_split<<<g2, NTH, SMEM_SZ>>>(Qh, Ql, Kh, Kl, nullptr,
                                     P, nullptr, nullptr, S_, E_, 0.03125f,
                                     (long)S_ * E_, (long)S_ * E_, (long)S_ * S_, 2);

    softmax_split<<<B_ * S_, 256>>>(P, Ph, Pl);

    // out = P @ V : per-batch M=2048, N=1024, K=2048 (B = V^T, NT form)
    dim3 g3(E_ / NT, S_ / MT, B_);
    gemm_split<<<g3, NTH, SMEM_SZ>>>(Ph, Pl, Vh, Vl, nullptr,
                                     out, nullptr, nullptr, E_, S_, 1.f,
                                     (long)S_ * S_, (long)E_ * S_, (long)S_ * E_, 3);
}